// round 8
// baseline (speedup 1.0000x reference)
#include <cuda_runtime.h>
#include <cuda_fp16.h>
#include <cstdint>
#include <cfloat>

// Problem constants
#define BQ     16
#define DIMD   128
#define TT     4096
#define NC     1024
#define NTOT   (BQ * TT)           // 65536 rows
#define QELEMS (BQ * DIMD * TT)    // 8388608 output quantized elems
#define NBLK   256                 // 256 blocks x 256 rows
#define FLAGCAP 4096

// Device scratch (no allocations allowed in kernel_launch)
__device__ float    g_halfnorm[NC];
__device__ float    g_ee[NC];          // strict sequential ||e||^2 (ref replication)
__device__ float    g_partial[NBLK];
__device__ unsigned g_used[NC];
__device__ int      g_flagcount;
__device__ int      g_flagged[FLAGCAP];
__device__ __align__(16) __half g_ef16[NC * DIMD];   // single fp16 codebook

// ---------------- helpers ----------------
__device__ __forceinline__ uint32_t smem_u32(const void* p) {
    uint32_t a;
    asm("{ .reg .u64 t; cvta.to.shared.u64 t, %1; cvt.u32.u64 %0, t; }"
        : "=r"(a) : "l"(p));
    return a;
}
__device__ __forceinline__ uint4 ldm_x4(uint32_t addr) {
    uint4 r;
    asm volatile("ldmatrix.sync.aligned.m8n8.x4.shared.b16 {%0,%1,%2,%3}, [%4];"
                 : "=r"(r.x), "=r"(r.y), "=r"(r.z), "=r"(r.w) : "r"(addr));
    return r;
}
__device__ __forceinline__ void mma16816(float4& c, const uint4& a,
                                         uint32_t b0, uint32_t b1) {
    asm volatile(
        "mma.sync.aligned.m16n8k16.row.col.f32.f16.f16.f32 "
        "{%0,%1,%2,%3}, {%4,%5,%6,%7}, {%8,%9}, {%0,%1,%2,%3};"
        : "+f"(c.x), "+f"(c.y), "+f"(c.z), "+f"(c.w)
        : "r"(a.x), "r"(a.y), "r"(a.z), "r"(a.w), "r"(b0), "r"(b1));
}
#define CP_ASYNC16(dst, src) \
    asm volatile("cp.async.cg.shared.global [%0], [%1], 16;" \
                 :: "r"(dst), "l"(src) : "memory")
#define CP_COMMIT() asm volatile("cp.async.commit_group;" ::: "memory")

// SMEM layout (bytes). Row stride 136 fp16 elements (272 B) -> conflict-free
// ldmatrix (bank group 4*row mod 32, disjoint 16B windows).
#define KPAD   136
#define OFF_XHI  0
#define OFF_XLO  69632              // 256*136*2
#define OFF_EH(buf) (139264 + (buf) * 34816)   // 128*136*2 each, double-buffered
#define OFF_HN   208896
#define OFF_XX   212992
#define OFF_SIDX 214016
#define OFF_RV1  215040
#define OFF_RV2  216064
#define OFF_RVI  217088
#define OFF_RED  218112
#define SMEM_MAIN 219136
#define OFF_QS   0                  // gather staging alias [256][129] f32 (132KB < XHI+XLO)

// score-units flag threshold: >= 4x the max fp16-split gap error (~2.5e-4)
// and >> the reference's fp32 d2 rounding grid (7.6e-6). Repair recomputes
// every flagged row with exact reference arithmetic.
#define STAU 1e-3f

// ---------------------------------------------------------------------------
// Kernel 0: halfnorm + strict-sequential ee + fp16 codebook
// ---------------------------------------------------------------------------
__global__ void prep_kernel(const float* __restrict__ embed) {
    int j = blockIdx.x * blockDim.x + threadIdx.x;
    if (j == 0) g_flagcount = 0;
    if (j < NC) {
        const float* row = embed + (size_t)j * DIMD;
        float s = 0.f;
        for (int k = 0; k < DIMD; k++) {
            float v = row[k];
            s = __fadd_rn(s, __fmul_rn(v, v));     // strict seq: ref replication
            g_ef16[j * DIMD + k] = __float2half_rn(v);
        }
        g_ee[j] = s;
        g_halfnorm[j] = 0.5f * s;
        g_used[j] = 0u;
    }
}

// ---------------------------------------------------------------------------
// Kernel 1: mma.sync fp16 2-split GEMM + argmax + fused gather/loss/output.
// Block = 256 t-rows of one batch, 256 threads, 8 warps x 32 rows.
// ---------------------------------------------------------------------------
__global__ __launch_bounds__(256, 1)
void vq_main_kernel(const float* __restrict__ x, const float* __restrict__ embed,
                    float* __restrict__ out) {
    extern __shared__ char smem[];
    const uint32_t smb = smem_u32(smem);
    float* hn    = (float*)(smem + OFF_HN);
    float* xx_sm = (float*)(smem + OFF_XX);
    int*   sidx  = (int*)(smem + OFF_SIDX);
    float* rv1   = (float*)(smem + OFF_RV1);
    float* rv2   = (float*)(smem + OFF_RV2);
    int*   rvi   = (int*)(smem + OFF_RVI);
    float* red   = (float*)(smem + OFF_RED);

    const int tid  = threadIdx.x;
    const int lane = tid & 31;
    const int w    = tid >> 5;
    const int b_   = blockIdx.x >> 4;
    const int t0   = (blockIdx.x & 15) * 256;

    // ---- 0. prefetch e chunk 0 (cp.async, buffer 0) ----
    {
        const char* src = (const char*)g_ef16;
#pragma unroll
        for (int i = 0; i < 8; i++) {
            int idx = tid + i * 256;               // 0..2047 16B segments
            int code = idx >> 4, ko = (idx & 15) * 8;
            uint32_t dst = smb + OFF_EH(0) + (uint32_t)(code * KPAD + ko) * 2;
            CP_ASYNC16(dst, src + idx * 16);
        }
        CP_COMMIT();
    }

    // ---- 1. load x column-slab, split fp16 hi/lo, per-row ||x||^2 ----
    {
        const float* xb = x + (size_t)b_ * DIMD * TT + t0 + tid;   // row m = tid
        float xx = 0.f;
        char* hrow = smem + OFF_XHI + tid * (KPAD * 2);
        char* lrow = smem + OFF_XLO + tid * (KPAD * 2);
#pragma unroll 4
        for (int k0 = 0; k0 < 128; k0 += 4) {
            float v0 = xb[(size_t)(k0 + 0) * TT];
            float v1_ = xb[(size_t)(k0 + 1) * TT];
            float v2_ = xb[(size_t)(k0 + 2) * TT];
            float v3 = xb[(size_t)(k0 + 3) * TT];
            xx += v0 * v0 + v1_ * v1_ + v2_ * v2_ + v3 * v3;
            __half h0 = __float2half_rn(v0);
            __half h1 = __float2half_rn(v1_);
            __half h2 = __float2half_rn(v2_);
            __half h3 = __float2half_rn(v3);
            __half2 hp0 = {h0, h1}, hp1 = {h2, h3};
            __half2 lp0 = {__float2half_rn(v0 - __half2float(h0)),
                           __float2half_rn(v1_ - __half2float(h1))};
            __half2 lp1 = {__float2half_rn(v2_ - __half2float(h2)),
                           __float2half_rn(v3 - __half2float(h3))};
            *(uint2*)(hrow + k0 * 2) =
                make_uint2(*(uint32_t*)&hp0, *(uint32_t*)&hp1);
            *(uint2*)(lrow + k0 * 2) =
                make_uint2(*(uint32_t*)&lp0, *(uint32_t*)&lp1);
        }
        xx_sm[tid] = xx;
    }
    for (int l = tid; l < NC; l += 256) hn[l] = g_halfnorm[l];
    __syncthreads();

    // ---- 2. preload A fragments (2 tiles x 8 ksteps x hi/lo) ----
    uint4 ahi[2][8], alo[2][8];
#pragma unroll
    for (int t = 0; t < 2; t++) {
#pragma unroll
        for (int ks = 0; ks < 8; ks++) {
            int rA = w * 32 + t * 16 + (lane & 7) + ((lane >> 3) & 1) * 8;
            int cA = ks * 16 + (lane >> 4) * 8;
            uint32_t off = (uint32_t)(rA * KPAD + cA) * 2;
            ahi[t][ks] = ldm_x4(smb + OFF_XHI + off);
            alo[t][ks] = ldm_x4(smb + OFF_XLO + off);
        }
    }

    float v1[4], v2[4];
    int   vi[4];
#pragma unroll
    for (int s = 0; s < 4; s++) { v1[s] = -FLT_MAX; v2[s] = -FLT_MAX; vi[s] = 0; }

    // ---- 3. code chunks of 128, double-buffered cp.async ----
    for (int chunk = 0; chunk < 8; chunk++) {
        const int buf = chunk & 1;
        if (chunk < 7) {                           // prefetch next into other buf
            const char* src = (const char*)(g_ef16 + (size_t)(chunk + 1) * 128 * DIMD);
            const uint32_t base = smb + OFF_EH(buf ^ 1);
#pragma unroll
            for (int i = 0; i < 8; i++) {
                int idx = tid + i * 256;
                int code = idx >> 4, ko = (idx & 15) * 8;
                CP_ASYNC16(base + (uint32_t)(code * KPAD + ko) * 2, src + idx * 16);
            }
            CP_COMMIT();
            asm volatile("cp.async.wait_group 1;" ::: "memory");
        } else {
            asm volatile("cp.async.wait_group 0;" ::: "memory");
        }
        __syncthreads();                           // chunk's buffer ready for all

        const uint32_t ebase = smb + OFF_EH(buf);
        for (int nt = 0; nt < 16; nt++) {
            const int n0 = nt * 8;
            float4 acc0 = {0.f, 0.f, 0.f, 0.f};
            float4 acc1 = {0.f, 0.f, 0.f, 0.f};
            const uint32_t brow = ebase +
                (uint32_t)((n0 + (lane & 7)) * KPAD + (lane >> 3) * 8) * 2;
#pragma unroll
            for (int kg = 0; kg < 4; kg++) {
                uint4 bh = ldm_x4(brow + kg * 64);
                mma16816(acc0, ahi[0][2 * kg],     bh.x, bh.y);
                mma16816(acc0, ahi[0][2 * kg + 1], bh.z, bh.w);
                mma16816(acc1, ahi[1][2 * kg],     bh.x, bh.y);
                mma16816(acc1, ahi[1][2 * kg + 1], bh.z, bh.w);
                mma16816(acc0, alo[0][2 * kg],     bh.x, bh.y);
                mma16816(acc0, alo[0][2 * kg + 1], bh.z, bh.w);
                mma16816(acc1, alo[1][2 * kg],     bh.x, bh.y);
                mma16816(acc1, alo[1][2 * kg + 1], bh.z, bh.w);
            }
            // epilogue: score = acc - halfnorm, top-2 update (ascending index)
            const int cg = chunk * 128 + n0 + (lane & 3) * 2;
            const float h0 = hn[cg], h1 = hn[cg + 1];
#pragma unroll
            for (int s = 0; s < 4; s++) {
                float s0, s1;
                if (s == 0)      { s0 = acc0.x - h0; s1 = acc0.y - h1; }
                else if (s == 1) { s0 = acc0.z - h0; s1 = acc0.w - h1; }
                else if (s == 2) { s0 = acc1.x - h0; s1 = acc1.y - h1; }
                else             { s0 = acc1.z - h0; s1 = acc1.w - h1; }
                if (s0 > v1[s]) { v2[s] = v1[s]; v1[s] = s0; vi[s] = cg; }
                else if (s0 > v2[s]) v2[s] = s0;
                if (s1 > v1[s]) { v2[s] = v1[s]; v1[s] = s1; vi[s] = cg + 1; }
                else if (s1 > v2[s]) v2[s] = s1;
            }
        }
        __syncthreads();                           // all reads of buf done
    }

    // ---- 4. quad merge (lanes sharing a row differ in lane&3) ----
#pragma unroll
    for (int s = 0; s < 4; s++) {
#pragma unroll
        for (int d = 1; d <= 2; d <<= 1) {
            float o1 = __shfl_xor_sync(0xFFFFFFFF, v1[s], d);
            float o2 = __shfl_xor_sync(0xFFFFFFFF, v2[s], d);
            int   oi = __shfl_xor_sync(0xFFFFFFFF, vi[s], d);
            if (o1 > v1[s]) { v2[s] = fmaxf(v1[s], o2); v1[s] = o1; vi[s] = oi; }
            else if (o1 == v1[s]) { v2[s] = v1[s]; if (oi < vi[s]) vi[s] = oi; }
            else v2[s] = fmaxf(v2[s], o1);
        }
        if ((lane & 3) == 0) {
            int row = w * 32 + (s >> 1) * 16 + (s & 1) * 8 + (lane >> 2);
            rv1[row] = v1[s];
            rv2[row] = v2[s];
            rvi[row] = vi[s];
        }
    }
    __syncthreads();

    // ---- 5. per-row results: flag / used / index / loss term ----
    {
        const int r = tid;
        const int n = b_ * TT + t0 + r;
        float xxv = xx_sm[r];
        float w1 = rv1[r], w2 = rv2[r];
        int   widx = rvi[r];
        if (w1 - w2 < STAU) {
            int slot = atomicAdd(&g_flagcount, 1);
            if (slot < FLAGCAP) g_flagged[slot] = n;
        } else {
            g_used[widx] = 1u;
        }
        out[QELEMS + n] = (float)widx;
        sidx[r] = widx;
        red[r]  = fmaf(-2.0f, w1, xxv);      // ||x - e||^2 for this row
    }
    __syncthreads();
    // loss partial reduce (256 values)
    if (tid < 128) red[tid] += red[tid + 128];
    __syncthreads();
    if (tid < 64) red[tid] += red[tid + 64];
    __syncthreads();
    if (tid < 32) {
        float s = red[tid] + red[tid + 32];
#pragma unroll
        for (int o = 16; o > 0; o >>= 1) s += __shfl_down_sync(0xFFFFFFFF, s, o);
        if (tid == 0) g_partial[blockIdx.x] = s;
    }

    // ---- 6. gather: stage selected codebook rows (alias smem), write [B,D,T] ----
    float* qs = (float*)(smem + OFF_QS);     // [256][stride 129]
    {
        const float4* er = (const float4*)(embed + (size_t)sidx[tid] * DIMD);
        float* qrow = qs + tid * 129;
#pragma unroll 8
        for (int q = 0; q < 32; q++) {
            float4 v = er[q];
            qrow[q * 4 + 0] = v.x; qrow[q * 4 + 1] = v.y;
            qrow[q * 4 + 2] = v.z; qrow[q * 4 + 3] = v.w;
        }
    }
    __syncthreads();
    {
        float* ob = out + (size_t)b_ * DIMD * TT + t0 + tid;
        const float* qrow = qs + tid * 129;
#pragma unroll 8
        for (int d = 0; d < 128; d++)
            ob[(size_t)d * TT] = qrow[d];     // coalesced in tid
    }
}

// ---------------------------------------------------------------------------
// Kernel 2: exact reference-arithmetic replication for flagged rows; rewrites
// index, quantized row, and used-mark for those rows.
// ---------------------------------------------------------------------------
__global__ __launch_bounds__(256, 1)
void repair_kernel(const float* __restrict__ x, const float* __restrict__ embed,
                   float* __restrict__ out) {
    __shared__ float xv[128];
    __shared__ float xxs;
    __shared__ float rv[256];
    __shared__ int   rix[256];
    const int tid = threadIdx.x;
    int nflag = *(volatile int*)&g_flagcount;
    if (nflag > FLAGCAP) nflag = FLAGCAP;

    for (int f = blockIdx.x; f < nflag; f += gridDim.x) {
        int n = g_flagged[f];
        int b = n >> 12, t = n & 4095;
        if (tid < 128) xv[tid] = x[(size_t)b * DIMD * TT + (size_t)tid * TT + t];
        __syncthreads();
        if (tid == 0) {
            float s = 0.f;
            for (int k = 0; k < 128; k++)
                s = __fadd_rn(s, __fmul_rn(xv[k], xv[k]));
            xxs = s;
        }
        __syncthreads();
        float xx = xxs;

        float bd = 3.4e38f;
        int   bj = 0;
#pragma unroll 1
        for (int q = 0; q < 4; q++) {
            int j = tid * 4 + q;
            const float* e = embed + (size_t)j * DIMD;
            float xe = 0.f;
            for (int k = 0; k < 128; k++)
                xe = __fadd_rn(xe, __fmul_rn(xv[k], e[k]));
            float s1 = __fadd_rn(xx, __fmul_rn(-2.0f, xe));
            float d2 = __fadd_rn(s1, g_ee[j]);
            if (d2 < bd) { bd = d2; bj = j; }
        }
        rv[tid] = bd; rix[tid] = bj;
        __syncthreads();
        for (int s = 128; s > 0; s >>= 1) {
            if (tid < s) {
                float ov = rv[tid + s]; int oj = rix[tid + s];
                if (ov < rv[tid] || (ov == rv[tid] && oj < rix[tid])) {
                    rv[tid] = ov; rix[tid] = oj;
                }
            }
            __syncthreads();
        }
        int idx = rix[0];
        if (tid == 0) {
            g_used[idx] = 1u;
            out[QELEMS + n] = (float)idx;
        }
        if (tid < 128)
            out[(size_t)b * DIMD * TT + (size_t)tid * TT + t] =
                embed[(size_t)idx * DIMD + tid];
        __syncthreads();
    }
}

// ---------------------------------------------------------------------------
// Kernel 3: deterministic final reduction -> loss, utilization
// ---------------------------------------------------------------------------
__global__ void finalize_kernel(float* __restrict__ out) {
    __shared__ float rs[512];
    __shared__ float us[512];
    int tid = threadIdx.x;
    rs[tid] = (tid < NBLK) ? g_partial[tid] : 0.f;
    us[tid] = (float)(g_used[tid] + g_used[tid + 512]);
    __syncthreads();
    for (int s = 256; s > 0; s >>= 1) {
        if (tid < s) { rs[tid] += rs[tid + s]; us[tid] += us[tid + s]; }
        __syncthreads();
    }
    if (tid == 0) {
        out[QELEMS + NTOT]     = 2.0f * rs[0] / (float)QELEMS;  // 2*mean(diff^2)
        out[QELEMS + NTOT + 1] = us[0] / (float)NC;
    }
}

// ---------------------------------------------------------------------------
extern "C" void kernel_launch(void* const* d_in, const int* in_sizes, int n_in,
                              void* d_out, int out_size) {
    (void)in_sizes; (void)n_in; (void)out_size;
    const float* x     = (const float*)d_in[0];
    const float* embed = (const float*)d_in[1];
    float*       out   = (float*)d_out;

    cudaFuncSetAttribute(vq_main_kernel,
                         cudaFuncAttributeMaxDynamicSharedMemorySize, SMEM_MAIN);

    prep_kernel<<<4, 256>>>(embed);
    vq_main_kernel<<<NBLK, 256, SMEM_MAIN>>>(x, embed, out);
    repair_kernel<<<148, 256>>>(x, embed, out);
    finalize_kernel<<<1, 512>>>(out);
}

// round 9
// speedup vs baseline: 1.0004x; 1.0004x over previous
#include <cuda_runtime.h>
#include <cuda_fp16.h>
#include <cstdint>
#include <cfloat>

// Problem constants
#define BQ     16
#define DIMD   128
#define TT     4096
#define NC     1024
#define NTOT   (BQ * TT)           // 65536 rows
#define QELEMS (BQ * DIMD * TT)    // 8388608 output quantized elems
#define NBLK   256                 // 256 blocks x 256 rows
#define FLAGCAP 4096

// Device scratch (no allocations allowed in kernel_launch)
__device__ float    g_halfnorm[NC];
__device__ float    g_ee[NC];          // strict sequential ||e||^2 (ref replication)
__device__ float    g_partial[NBLK];
__device__ unsigned g_used[NC];
__device__ int      g_flagcount;
__device__ int      g_flagged[FLAGCAP];
__device__ __align__(16) __half g_ef16[NC * DIMD];   // single fp16 codebook

// ---------------- helpers ----------------
__device__ __forceinline__ uint32_t smem_u32(const void* p) {
    uint32_t a;
    asm("{ .reg .u64 t; cvta.to.shared.u64 t, %1; cvt.u32.u64 %0, t; }"
        : "=r"(a) : "l"(p));
    return a;
}
__device__ __forceinline__ uint4 ldm_x4(uint32_t addr) {
    uint4 r;
    asm volatile("ldmatrix.sync.aligned.m8n8.x4.shared.b16 {%0,%1,%2,%3}, [%4];"
                 : "=r"(r.x), "=r"(r.y), "=r"(r.z), "=r"(r.w) : "r"(addr));
    return r;
}
__device__ __forceinline__ void mma16816(float4& c, const uint4& a,
                                         uint32_t b0, uint32_t b1) {
    asm volatile(
        "mma.sync.aligned.m16n8k16.row.col.f32.f16.f16.f32 "
        "{%0,%1,%2,%3}, {%4,%5,%6,%7}, {%8,%9}, {%0,%1,%2,%3};"
        : "+f"(c.x), "+f"(c.y), "+f"(c.z), "+f"(c.w)
        : "r"(a.x), "r"(a.y), "r"(a.z), "r"(a.w), "r"(b0), "r"(b1));
}
#define CP_ASYNC16(dst, src) \
    asm volatile("cp.async.cg.shared.global [%0], [%1], 16;" \
                 :: "r"(dst), "l"(src) : "memory")
#define CP_COMMIT() asm volatile("cp.async.commit_group;" ::: "memory")

// SMEM layout (bytes). Row stride 136 fp16 elements (272 B) -> conflict-free
// ldmatrix (bank group 4*row mod 32, disjoint 16B windows).
#define KPAD   136
#define OFF_XHI  0
#define OFF_XLO  69632              // 256*136*2
#define OFF_EH(buf) (139264 + (buf) * 34816)   // 128*136*2 each, double-buffered
#define OFF_HN   208896
#define OFF_XX   212992
#define OFF_SIDX 214016
#define OFF_RV1  215040
#define OFF_RV2  216064
#define OFF_RVI  217088
#define OFF_RED  218112
#define SMEM_MAIN 219136
#define OFF_QS   0                  // gather staging alias [256][129] f32 (132KB < XHI+XLO)

// score-units flag threshold: >= 4x the max fp16-split gap error (~2.5e-4)
// and >> the reference's fp32 d2 rounding grid (7.6e-6). Repair recomputes
// every flagged row with exact reference arithmetic.
#define STAU 1e-3f

// ---------------------------------------------------------------------------
// Kernel 0: halfnorm + strict-sequential ee + fp16 codebook
// ---------------------------------------------------------------------------
__global__ void prep_kernel(const float* __restrict__ embed) {
    int j = blockIdx.x * blockDim.x + threadIdx.x;
    if (j == 0) g_flagcount = 0;
    if (j < NC) {
        const float* row = embed + (size_t)j * DIMD;
        float s = 0.f;
        for (int k = 0; k < DIMD; k++) {
            float v = row[k];
            s = __fadd_rn(s, __fmul_rn(v, v));     // strict seq: ref replication
            g_ef16[j * DIMD + k] = __float2half_rn(v);
        }
        g_ee[j] = s;
        g_halfnorm[j] = 0.5f * s;
        g_used[j] = 0u;
    }
}

// ---------------------------------------------------------------------------
// Kernel 1: mma.sync fp16 2-split GEMM + argmax + fused gather/loss/output.
// Block = 256 t-rows of one batch, 256 threads, 8 warps x 32 rows.
// ---------------------------------------------------------------------------
__global__ __launch_bounds__(256, 1)
void vq_main_kernel(const float* __restrict__ x, const float* __restrict__ embed,
                    float* __restrict__ out) {
    extern __shared__ char smem[];
    const uint32_t smb = smem_u32(smem);
    float* hn    = (float*)(smem + OFF_HN);
    float* xx_sm = (float*)(smem + OFF_XX);
    int*   sidx  = (int*)(smem + OFF_SIDX);
    float* rv1   = (float*)(smem + OFF_RV1);
    float* rv2   = (float*)(smem + OFF_RV2);
    int*   rvi   = (int*)(smem + OFF_RVI);
    float* red   = (float*)(smem + OFF_RED);

    const int tid  = threadIdx.x;
    const int lane = tid & 31;
    const int w    = tid >> 5;
    const int b_   = blockIdx.x >> 4;
    const int t0   = (blockIdx.x & 15) * 256;

    // ---- 0. prefetch e chunk 0 (cp.async, buffer 0) ----
    {
        const char* src = (const char*)g_ef16;
#pragma unroll
        for (int i = 0; i < 8; i++) {
            int idx = tid + i * 256;               // 0..2047 16B segments
            int code = idx >> 4, ko = (idx & 15) * 8;
            uint32_t dst = smb + OFF_EH(0) + (uint32_t)(code * KPAD + ko) * 2;
            CP_ASYNC16(dst, src + idx * 16);
        }
        CP_COMMIT();
    }

    // ---- 1. load x column-slab, split fp16 hi/lo, per-row ||x||^2 ----
    {
        const float* xb = x + (size_t)b_ * DIMD * TT + t0 + tid;   // row m = tid
        float xx = 0.f;
        char* hrow = smem + OFF_XHI + tid * (KPAD * 2);
        char* lrow = smem + OFF_XLO + tid * (KPAD * 2);
#pragma unroll 4
        for (int k0 = 0; k0 < 128; k0 += 4) {
            float v0 = xb[(size_t)(k0 + 0) * TT];
            float v1_ = xb[(size_t)(k0 + 1) * TT];
            float v2_ = xb[(size_t)(k0 + 2) * TT];
            float v3 = xb[(size_t)(k0 + 3) * TT];
            xx += v0 * v0 + v1_ * v1_ + v2_ * v2_ + v3 * v3;
            __half h0 = __float2half_rn(v0);
            __half h1 = __float2half_rn(v1_);
            __half h2 = __float2half_rn(v2_);
            __half h3 = __float2half_rn(v3);
            __half2 hp0 = {h0, h1}, hp1 = {h2, h3};
            __half2 lp0 = {__float2half_rn(v0 - __half2float(h0)),
                           __float2half_rn(v1_ - __half2float(h1))};
            __half2 lp1 = {__float2half_rn(v2_ - __half2float(h2)),
                           __float2half_rn(v3 - __half2float(h3))};
            *(uint2*)(hrow + k0 * 2) =
                make_uint2(*(uint32_t*)&hp0, *(uint32_t*)&hp1);
            *(uint2*)(lrow + k0 * 2) =
                make_uint2(*(uint32_t*)&lp0, *(uint32_t*)&lp1);
        }
        xx_sm[tid] = xx;
    }
    for (int l = tid; l < NC; l += 256) hn[l] = g_halfnorm[l];
    __syncthreads();

    // ---- 2. preload A fragments (2 tiles x 8 ksteps x hi/lo) ----
    uint4 ahi[2][8], alo[2][8];
#pragma unroll
    for (int t = 0; t < 2; t++) {
#pragma unroll
        for (int ks = 0; ks < 8; ks++) {
            int rA = w * 32 + t * 16 + (lane & 7) + ((lane >> 3) & 1) * 8;
            int cA = ks * 16 + (lane >> 4) * 8;
            uint32_t off = (uint32_t)(rA * KPAD + cA) * 2;
            ahi[t][ks] = ldm_x4(smb + OFF_XHI + off);
            alo[t][ks] = ldm_x4(smb + OFF_XLO + off);
        }
    }

    float v1[4], v2[4];
    int   vi[4];
#pragma unroll
    for (int s = 0; s < 4; s++) { v1[s] = -FLT_MAX; v2[s] = -FLT_MAX; vi[s] = 0; }

    // ---- 3. code chunks of 128, double-buffered cp.async ----
    for (int chunk = 0; chunk < 8; chunk++) {
        const int buf = chunk & 1;
        if (chunk < 7) {                           // prefetch next into other buf
            const char* src = (const char*)(g_ef16 + (size_t)(chunk + 1) * 128 * DIMD);
            const uint32_t base = smb + OFF_EH(buf ^ 1);
#pragma unroll
            for (int i = 0; i < 8; i++) {
                int idx = tid + i * 256;
                int code = idx >> 4, ko = (idx & 15) * 8;
                CP_ASYNC16(base + (uint32_t)(code * KPAD + ko) * 2, src + idx * 16);
            }
            CP_COMMIT();
            asm volatile("cp.async.wait_group 1;" ::: "memory");
        } else {
            asm volatile("cp.async.wait_group 0;" ::: "memory");
        }
        __syncthreads();                           // chunk's buffer ready for all

        const uint32_t ebase = smb + OFF_EH(buf);
        for (int nt = 0; nt < 16; nt++) {
            const int n0 = nt * 8;
            float4 acc0 = {0.f, 0.f, 0.f, 0.f};
            float4 acc1 = {0.f, 0.f, 0.f, 0.f};
            const uint32_t brow = ebase +
                (uint32_t)((n0 + (lane & 7)) * KPAD + (lane >> 3) * 8) * 2;
#pragma unroll
            for (int kg = 0; kg < 4; kg++) {
                uint4 bh = ldm_x4(brow + kg * 64);
                mma16816(acc0, ahi[0][2 * kg],     bh.x, bh.y);
                mma16816(acc0, ahi[0][2 * kg + 1], bh.z, bh.w);
                mma16816(acc1, ahi[1][2 * kg],     bh.x, bh.y);
                mma16816(acc1, ahi[1][2 * kg + 1], bh.z, bh.w);
                mma16816(acc0, alo[0][2 * kg],     bh.x, bh.y);
                mma16816(acc0, alo[0][2 * kg + 1], bh.z, bh.w);
                mma16816(acc1, alo[1][2 * kg],     bh.x, bh.y);
                mma16816(acc1, alo[1][2 * kg + 1], bh.z, bh.w);
            }
            // epilogue: score = acc - halfnorm, top-2 update (ascending index)
            const int cg = chunk * 128 + n0 + (lane & 3) * 2;
            const float h0 = hn[cg], h1 = hn[cg + 1];
#pragma unroll
            for (int s = 0; s < 4; s++) {
                float s0, s1;
                if (s == 0)      { s0 = acc0.x - h0; s1 = acc0.y - h1; }
                else if (s == 1) { s0 = acc0.z - h0; s1 = acc0.w - h1; }
                else if (s == 2) { s0 = acc1.x - h0; s1 = acc1.y - h1; }
                else             { s0 = acc1.z - h0; s1 = acc1.w - h1; }
                if (s0 > v1[s]) { v2[s] = v1[s]; v1[s] = s0; vi[s] = cg; }
                else if (s0 > v2[s]) v2[s] = s0;
                if (s1 > v1[s]) { v2[s] = v1[s]; v1[s] = s1; vi[s] = cg + 1; }
                else if (s1 > v2[s]) v2[s] = s1;
            }
        }
        __syncthreads();                           // all reads of buf done
    }

    // ---- 4. quad merge (lanes sharing a row differ in lane&3) ----
#pragma unroll
    for (int s = 0; s < 4; s++) {
#pragma unroll
        for (int d = 1; d <= 2; d <<= 1) {
            float o1 = __shfl_xor_sync(0xFFFFFFFF, v1[s], d);
            float o2 = __shfl_xor_sync(0xFFFFFFFF, v2[s], d);
            int   oi = __shfl_xor_sync(0xFFFFFFFF, vi[s], d);
            if (o1 > v1[s]) { v2[s] = fmaxf(v1[s], o2); v1[s] = o1; vi[s] = oi; }
            else if (o1 == v1[s]) { v2[s] = v1[s]; if (oi < vi[s]) vi[s] = oi; }
            else v2[s] = fmaxf(v2[s], o1);
        }
        if ((lane & 3) == 0) {
            int row = w * 32 + (s >> 1) * 16 + (s & 1) * 8 + (lane >> 2);
            rv1[row] = v1[s];
            rv2[row] = v2[s];
            rvi[row] = vi[s];
        }
    }
    __syncthreads();

    // ---- 5. per-row results: flag / used / index / loss term ----
    {
        const int r = tid;
        const int n = b_ * TT + t0 + r;
        float xxv = xx_sm[r];
        float w1 = rv1[r], w2 = rv2[r];
        int   widx = rvi[r];
        if (w1 - w2 < STAU) {
            int slot = atomicAdd(&g_flagcount, 1);
            if (slot < FLAGCAP) g_flagged[slot] = n;
        } else {
            g_used[widx] = 1u;
        }
        out[QELEMS + n] = (float)widx;
        sidx[r] = widx;
        red[r]  = fmaf(-2.0f, w1, xxv);      // ||x - e||^2 for this row
    }
    __syncthreads();
    // loss partial reduce (256 values)
    if (tid < 128) red[tid] += red[tid + 128];
    __syncthreads();
    if (tid < 64) red[tid] += red[tid + 64];
    __syncthreads();
    if (tid < 32) {
        float s = red[tid] + red[tid + 32];
#pragma unroll
        for (int o = 16; o > 0; o >>= 1) s += __shfl_down_sync(0xFFFFFFFF, s, o);
        if (tid == 0) g_partial[blockIdx.x] = s;
    }

    // ---- 6. gather: stage selected codebook rows (alias smem), write [B,D,T] ----
    float* qs = (float*)(smem + OFF_QS);     // [256][stride 129]
    {
        const float4* er = (const float4*)(embed + (size_t)sidx[tid] * DIMD);
        float* qrow = qs + tid * 129;
#pragma unroll 8
        for (int q = 0; q < 32; q++) {
            float4 v = er[q];
            qrow[q * 4 + 0] = v.x; qrow[q * 4 + 1] = v.y;
            qrow[q * 4 + 2] = v.z; qrow[q * 4 + 3] = v.w;
        }
    }
    __syncthreads();
    {
        float* ob = out + (size_t)b_ * DIMD * TT + t0 + tid;
        const float* qrow = qs + tid * 129;
#pragma unroll 8
        for (int d = 0; d < 128; d++)
            ob[(size_t)d * TT] = qrow[d];     // coalesced in tid
    }
}

// ---------------------------------------------------------------------------
// Kernel 2: exact reference-arithmetic replication for flagged rows; rewrites
// index, quantized row, and used-mark for those rows.
// ---------------------------------------------------------------------------
__global__ __launch_bounds__(256, 1)
void repair_kernel(const float* __restrict__ x, const float* __restrict__ embed,
                   float* __restrict__ out) {
    __shared__ float xv[128];
    __shared__ float xxs;
    __shared__ float rv[256];
    __shared__ int   rix[256];
    const int tid = threadIdx.x;
    int nflag = *(volatile int*)&g_flagcount;
    if (nflag > FLAGCAP) nflag = FLAGCAP;

    for (int f = blockIdx.x; f < nflag; f += gridDim.x) {
        int n = g_flagged[f];
        int b = n >> 12, t = n & 4095;
        if (tid < 128) xv[tid] = x[(size_t)b * DIMD * TT + (size_t)tid * TT + t];
        __syncthreads();
        if (tid == 0) {
            float s = 0.f;
            for (int k = 0; k < 128; k++)
                s = __fadd_rn(s, __fmul_rn(xv[k], xv[k]));
            xxs = s;
        }
        __syncthreads();
        float xx = xxs;

        float bd = 3.4e38f;
        int   bj = 0;
#pragma unroll 1
        for (int q = 0; q < 4; q++) {
            int j = tid * 4 + q;
            const float* e = embed + (size_t)j * DIMD;
            float xe = 0.f;
            for (int k = 0; k < 128; k++)
                xe = __fadd_rn(xe, __fmul_rn(xv[k], e[k]));
            float s1 = __fadd_rn(xx, __fmul_rn(-2.0f, xe));
            float d2 = __fadd_rn(s1, g_ee[j]);
            if (d2 < bd) { bd = d2; bj = j; }
        }
        rv[tid] = bd; rix[tid] = bj;
        __syncthreads();
        for (int s = 128; s > 0; s >>= 1) {
            if (tid < s) {
                float ov = rv[tid + s]; int oj = rix[tid + s];
                if (ov < rv[tid] || (ov == rv[tid] && oj < rix[tid])) {
                    rv[tid] = ov; rix[tid] = oj;
                }
            }
            __syncthreads();
        }
        int idx = rix[0];
        if (tid == 0) {
            g_used[idx] = 1u;
            out[QELEMS + n] = (float)idx;
        }
        if (tid < 128)
            out[(size_t)b * DIMD * TT + (size_t)tid * TT + t] =
                embed[(size_t)idx * DIMD + tid];
        __syncthreads();
    }
}

// ---------------------------------------------------------------------------
// Kernel 3: deterministic final reduction -> loss, utilization
// ---------------------------------------------------------------------------
__global__ void finalize_kernel(float* __restrict__ out) {
    __shared__ float rs[512];
    __shared__ float us[512];
    int tid = threadIdx.x;
    rs[tid] = (tid < NBLK) ? g_partial[tid] : 0.f;
    us[tid] = (float)(g_used[tid] + g_used[tid + 512]);
    __syncthreads();
    for (int s = 256; s > 0; s >>= 1) {
        if (tid < s) { rs[tid] += rs[tid + s]; us[tid] += us[tid + s]; }
        __syncthreads();
    }
    if (tid == 0) {
        out[QELEMS + NTOT]     = 2.0f * rs[0] / (float)QELEMS;  // 2*mean(diff^2)
        out[QELEMS + NTOT + 1] = us[0] / (float)NC;
    }
}

// ---------------------------------------------------------------------------
extern "C" void kernel_launch(void* const* d_in, const int* in_sizes, int n_in,
                              void* d_out, int out_size) {
    (void)in_sizes; (void)n_in; (void)out_size;
    const float* x     = (const float*)d_in[0];
    const float* embed = (const float*)d_in[1];
    float*       out   = (float*)d_out;

    cudaFuncSetAttribute(vq_main_kernel,
                         cudaFuncAttributeMaxDynamicSharedMemorySize, SMEM_MAIN);

    prep_kernel<<<4, 256>>>(embed);
    vq_main_kernel<<<NBLK, 256, SMEM_MAIN>>>(x, embed, out);
    repair_kernel<<<148, 256>>>(x, embed, out);
    finalize_kernel<<<1, 512>>>(out);
}

// round 10
// speedup vs baseline: 1.0057x; 1.0053x over previous
#include <cuda_runtime.h>
#include <cuda_fp16.h>
#include <cstdint>
#include <cfloat>

// Problem constants
#define BQ     16
#define DIMD   128
#define TT     4096
#define NC     1024
#define NTOT   (BQ * TT)           // 65536 rows
#define QELEMS (BQ * DIMD * TT)    // 8388608 output quantized elems
#define NBLK   256                 // 256 blocks x 256 rows
#define FLAGCAP 4096

// Device scratch (no allocations allowed in kernel_launch)
__device__ float    g_halfnorm[NC];
__device__ float    g_ee[NC];          // strict sequential ||e||^2 (ref replication)
__device__ float    g_partial[NBLK];
__device__ unsigned g_used[NC];
__device__ int      g_flagcount;
__device__ int      g_flagged[FLAGCAP];
__device__ __align__(16) __half g_ef16[NC * DIMD];   // single fp16 codebook

// ---------------- helpers ----------------
__device__ __forceinline__ uint32_t smem_u32(const void* p) {
    uint32_t a;
    asm("{ .reg .u64 t; cvta.to.shared.u64 t, %1; cvt.u32.u64 %0, t; }"
        : "=r"(a) : "l"(p));
    return a;
}
__device__ __forceinline__ uint4 ldm_x4(uint32_t addr) {
    uint4 r;
    asm volatile("ldmatrix.sync.aligned.m8n8.x4.shared.b16 {%0,%1,%2,%3}, [%4];"
                 : "=r"(r.x), "=r"(r.y), "=r"(r.z), "=r"(r.w) : "r"(addr));
    return r;
}
__device__ __forceinline__ void mma16816(float4& c, const uint4& a,
                                         uint32_t b0, uint32_t b1) {
    asm volatile(
        "mma.sync.aligned.m16n8k16.row.col.f32.f16.f16.f32 "
        "{%0,%1,%2,%3}, {%4,%5,%6,%7}, {%8,%9}, {%0,%1,%2,%3};"
        : "+f"(c.x), "+f"(c.y), "+f"(c.z), "+f"(c.w)
        : "r"(a.x), "r"(a.y), "r"(a.z), "r"(a.w), "r"(b0), "r"(b1));
}
#define CP_ASYNC16(dst, src) \
    asm volatile("cp.async.cg.shared.global [%0], [%1], 16;" \
                 :: "r"(dst), "l"(src) : "memory")
#define CP_COMMIT() asm volatile("cp.async.commit_group;" ::: "memory")

// SMEM layout (bytes). Row stride 136 fp16 elements (272 B) -> conflict-free
// ldmatrix (bank group 4*row mod 32, disjoint 16B windows).
#define KPAD   136
#define OFF_XHI  0
#define OFF_XLO  69632              // 256*136*2
#define OFF_EH(buf) (139264 + (buf) * 34816)   // 128*136*2 each, double-buffered
#define OFF_HN   208896
#define OFF_XX   212992
#define OFF_SIDX 214016
#define OFF_RV1  215040
#define OFF_RV2  216064
#define OFF_RVI  217088
#define OFF_RED  218112
#define SMEM_MAIN 219136
#define OFF_QS   0                  // gather staging alias [256][129] f32 (132KB < XHI+XLO)

// score-units flag threshold: >= 4x the max fp16-split gap error (~2.5e-4)
// and >> the reference's fp32 d2 rounding grid (7.6e-6). Repair recomputes
// every flagged row with exact reference arithmetic.
#define STAU 1e-3f

// ---------------------------------------------------------------------------
// Kernel 0: halfnorm + strict-sequential ee + fp16 codebook
// ---------------------------------------------------------------------------
__global__ void prep_kernel(const float* __restrict__ embed) {
    int j = blockIdx.x * blockDim.x + threadIdx.x;
    if (j == 0) g_flagcount = 0;
    if (j < NC) {
        const float* row = embed + (size_t)j * DIMD;
        float s = 0.f;
        for (int k = 0; k < DIMD; k++) {
            float v = row[k];
            s = __fadd_rn(s, __fmul_rn(v, v));     // strict seq: ref replication
            g_ef16[j * DIMD + k] = __float2half_rn(v);
        }
        g_ee[j] = s;
        g_halfnorm[j] = 0.5f * s;
        g_used[j] = 0u;
    }
}

// ---------------------------------------------------------------------------
// Kernel 1: mma.sync fp16 2-split GEMM + argmax + fused gather/loss/output.
// Block = 256 t-rows of one batch, 256 threads, 8 warps x 32 rows.
// ---------------------------------------------------------------------------
__global__ __launch_bounds__(256, 1)
void vq_main_kernel(const float* __restrict__ x, const float* __restrict__ embed,
                    float* __restrict__ out) {
    extern __shared__ char smem[];
    const uint32_t smb = smem_u32(smem);
    float* hn    = (float*)(smem + OFF_HN);
    float* xx_sm = (float*)(smem + OFF_XX);
    int*   sidx  = (int*)(smem + OFF_SIDX);
    float* rv1   = (float*)(smem + OFF_RV1);
    float* rv2   = (float*)(smem + OFF_RV2);
    int*   rvi   = (int*)(smem + OFF_RVI);
    float* red   = (float*)(smem + OFF_RED);

    const int tid  = threadIdx.x;
    const int lane = tid & 31;
    const int w    = tid >> 5;
    const int b_   = blockIdx.x >> 4;
    const int t0   = (blockIdx.x & 15) * 256;

    // ---- 0. prefetch e chunk 0 (cp.async, buffer 0) ----
    {
        const char* src = (const char*)g_ef16;
#pragma unroll
        for (int i = 0; i < 8; i++) {
            int idx = tid + i * 256;               // 0..2047 16B segments
            int code = idx >> 4, ko = (idx & 15) * 8;
            uint32_t dst = smb + OFF_EH(0) + (uint32_t)(code * KPAD + ko) * 2;
            CP_ASYNC16(dst, src + idx * 16);
        }
        CP_COMMIT();
    }

    // ---- 1. load x column-slab, split fp16 hi/lo, per-row ||x||^2 ----
    {
        const float* xb = x + (size_t)b_ * DIMD * TT + t0 + tid;   // row m = tid
        float xx = 0.f;
        char* hrow = smem + OFF_XHI + tid * (KPAD * 2);
        char* lrow = smem + OFF_XLO + tid * (KPAD * 2);
#pragma unroll 4
        for (int k0 = 0; k0 < 128; k0 += 4) {
            float v0 = xb[(size_t)(k0 + 0) * TT];
            float v1_ = xb[(size_t)(k0 + 1) * TT];
            float v2_ = xb[(size_t)(k0 + 2) * TT];
            float v3 = xb[(size_t)(k0 + 3) * TT];
            xx += v0 * v0 + v1_ * v1_ + v2_ * v2_ + v3 * v3;
            __half h0 = __float2half_rn(v0);
            __half h1 = __float2half_rn(v1_);
            __half h2 = __float2half_rn(v2_);
            __half h3 = __float2half_rn(v3);
            __half2 hp0 = {h0, h1}, hp1 = {h2, h3};
            __half2 lp0 = {__float2half_rn(v0 - __half2float(h0)),
                           __float2half_rn(v1_ - __half2float(h1))};
            __half2 lp1 = {__float2half_rn(v2_ - __half2float(h2)),
                           __float2half_rn(v3 - __half2float(h3))};
            *(uint2*)(hrow + k0 * 2) =
                make_uint2(*(uint32_t*)&hp0, *(uint32_t*)&hp1);
            *(uint2*)(lrow + k0 * 2) =
                make_uint2(*(uint32_t*)&lp0, *(uint32_t*)&lp1);
        }
        xx_sm[tid] = xx;
    }
    for (int l = tid; l < NC; l += 256) hn[l] = g_halfnorm[l];
    __syncthreads();

    // ---- 2. preload A fragments (2 tiles x 8 ksteps x hi/lo) ----
    uint4 ahi[2][8], alo[2][8];
#pragma unroll
    for (int t = 0; t < 2; t++) {
#pragma unroll
        for (int ks = 0; ks < 8; ks++) {
            int rA = w * 32 + t * 16 + (lane & 7) + ((lane >> 3) & 1) * 8;
            int cA = ks * 16 + (lane >> 4) * 8;
            uint32_t off = (uint32_t)(rA * KPAD + cA) * 2;
            ahi[t][ks] = ldm_x4(smb + OFF_XHI + off);
            alo[t][ks] = ldm_x4(smb + OFF_XLO + off);
        }
    }

    float v1[4], v2[4];
    int   vi[4];
#pragma unroll
    for (int s = 0; s < 4; s++) { v1[s] = -FLT_MAX; v2[s] = -FLT_MAX; vi[s] = 0; }

    // ---- 3. code chunks of 128, double-buffered cp.async ----
    for (int chunk = 0; chunk < 8; chunk++) {
        const int buf = chunk & 1;
        if (chunk < 7) {                           // prefetch next into other buf
            const char* src = (const char*)(g_ef16 + (size_t)(chunk + 1) * 128 * DIMD);
            const uint32_t base = smb + OFF_EH(buf ^ 1);
#pragma unroll
            for (int i = 0; i < 8; i++) {
                int idx = tid + i * 256;
                int code = idx >> 4, ko = (idx & 15) * 8;
                CP_ASYNC16(base + (uint32_t)(code * KPAD + ko) * 2, src + idx * 16);
            }
            CP_COMMIT();
            asm volatile("cp.async.wait_group 1;" ::: "memory");
        } else {
            asm volatile("cp.async.wait_group 0;" ::: "memory");
        }
        __syncthreads();                           // chunk's buffer ready for all

        const uint32_t ebase = smb + OFF_EH(buf);
        for (int nt = 0; nt < 16; nt++) {
            const int n0 = nt * 8;
            float4 acc0 = {0.f, 0.f, 0.f, 0.f};
            float4 acc1 = {0.f, 0.f, 0.f, 0.f};
            const uint32_t brow = ebase +
                (uint32_t)((n0 + (lane & 7)) * KPAD + (lane >> 3) * 8) * 2;
#pragma unroll
            for (int kg = 0; kg < 4; kg++) {
                uint4 bh = ldm_x4(brow + kg * 64);
                mma16816(acc0, ahi[0][2 * kg],     bh.x, bh.y);
                mma16816(acc0, ahi[0][2 * kg + 1], bh.z, bh.w);
                mma16816(acc1, ahi[1][2 * kg],     bh.x, bh.y);
                mma16816(acc1, ahi[1][2 * kg + 1], bh.z, bh.w);
                mma16816(acc0, alo[0][2 * kg],     bh.x, bh.y);
                mma16816(acc0, alo[0][2 * kg + 1], bh.z, bh.w);
                mma16816(acc1, alo[1][2 * kg],     bh.x, bh.y);
                mma16816(acc1, alo[1][2 * kg + 1], bh.z, bh.w);
            }
            // epilogue: score = acc - halfnorm, top-2 update (ascending index)
            const int cg = chunk * 128 + n0 + (lane & 3) * 2;
            const float h0 = hn[cg], h1 = hn[cg + 1];
#pragma unroll
            for (int s = 0; s < 4; s++) {
                float s0, s1;
                if (s == 0)      { s0 = acc0.x - h0; s1 = acc0.y - h1; }
                else if (s == 1) { s0 = acc0.z - h0; s1 = acc0.w - h1; }
                else if (s == 2) { s0 = acc1.x - h0; s1 = acc1.y - h1; }
                else             { s0 = acc1.z - h0; s1 = acc1.w - h1; }
                if (s0 > v1[s]) { v2[s] = v1[s]; v1[s] = s0; vi[s] = cg; }
                else if (s0 > v2[s]) v2[s] = s0;
                if (s1 > v1[s]) { v2[s] = v1[s]; v1[s] = s1; vi[s] = cg + 1; }
                else if (s1 > v2[s]) v2[s] = s1;
            }
        }
        __syncthreads();                           // all reads of buf done
    }

    // ---- 4. quad merge (lanes sharing a row differ in lane&3) ----
#pragma unroll
    for (int s = 0; s < 4; s++) {
#pragma unroll
        for (int d = 1; d <= 2; d <<= 1) {
            float o1 = __shfl_xor_sync(0xFFFFFFFF, v1[s], d);
            float o2 = __shfl_xor_sync(0xFFFFFFFF, v2[s], d);
            int   oi = __shfl_xor_sync(0xFFFFFFFF, vi[s], d);
            if (o1 > v1[s]) { v2[s] = fmaxf(v1[s], o2); v1[s] = o1; vi[s] = oi; }
            else if (o1 == v1[s]) { v2[s] = v1[s]; if (oi < vi[s]) vi[s] = oi; }
            else v2[s] = fmaxf(v2[s], o1);
        }
        if ((lane & 3) == 0) {
            int row = w * 32 + (s >> 1) * 16 + (s & 1) * 8 + (lane >> 2);
            rv1[row] = v1[s];
            rv2[row] = v2[s];
            rvi[row] = vi[s];
        }
    }
    __syncthreads();

    // ---- 5. per-row results: flag / used / index / loss term ----
    {
        const int r = tid;
        const int n = b_ * TT + t0 + r;
        float xxv = xx_sm[r];
        float w1 = rv1[r], w2 = rv2[r];
        int   widx = rvi[r];
        if (w1 - w2 < STAU) {
            int slot = atomicAdd(&g_flagcount, 1);
            if (slot < FLAGCAP) g_flagged[slot] = n;
        } else {
            g_used[widx] = 1u;
        }
        out[QELEMS + n] = (float)widx;
        sidx[r] = widx;
        red[r]  = fmaf(-2.0f, w1, xxv);      // ||x - e||^2 for this row
    }
    __syncthreads();
    // loss partial reduce (256 values)
    if (tid < 128) red[tid] += red[tid + 128];
    __syncthreads();
    if (tid < 64) red[tid] += red[tid + 64];
    __syncthreads();
    if (tid < 32) {
        float s = red[tid] + red[tid + 32];
#pragma unroll
        for (int o = 16; o > 0; o >>= 1) s += __shfl_down_sync(0xFFFFFFFF, s, o);
        if (tid == 0) g_partial[blockIdx.x] = s;
    }

    // ---- 6. gather: stage selected codebook rows (alias smem), write [B,D,T] ----
    float* qs = (float*)(smem + OFF_QS);     // [256][stride 129]
    {
        const float4* er = (const float4*)(embed + (size_t)sidx[tid] * DIMD);
        float* qrow = qs + tid * 129;
#pragma unroll 8
        for (int q = 0; q < 32; q++) {
            float4 v = er[q];
            qrow[q * 4 + 0] = v.x; qrow[q * 4 + 1] = v.y;
            qrow[q * 4 + 2] = v.z; qrow[q * 4 + 3] = v.w;
        }
    }
    __syncthreads();
    {
        float* ob = out + (size_t)b_ * DIMD * TT + t0 + tid;
        const float* qrow = qs + tid * 129;
#pragma unroll 8
        for (int d = 0; d < 128; d++)
            ob[(size_t)d * TT] = qrow[d];     // coalesced in tid
    }
}

// ---------------------------------------------------------------------------
// Kernel 2: exact reference-arithmetic replication for flagged rows; rewrites
// index, quantized row, and used-mark for those rows.
// ---------------------------------------------------------------------------
__global__ __launch_bounds__(256, 1)
void repair_kernel(const float* __restrict__ x, const float* __restrict__ embed,
                   float* __restrict__ out) {
    __shared__ float xv[128];
    __shared__ float xxs;
    __shared__ float rv[256];
    __shared__ int   rix[256];
    const int tid = threadIdx.x;
    int nflag = *(volatile int*)&g_flagcount;
    if (nflag > FLAGCAP) nflag = FLAGCAP;

    for (int f = blockIdx.x; f < nflag; f += gridDim.x) {
        int n = g_flagged[f];
        int b = n >> 12, t = n & 4095;
        if (tid < 128) xv[tid] = x[(size_t)b * DIMD * TT + (size_t)tid * TT + t];
        __syncthreads();
        if (tid == 0) {
            float s = 0.f;
            for (int k = 0; k < 128; k++)
                s = __fadd_rn(s, __fmul_rn(xv[k], xv[k]));
            xxs = s;
        }
        __syncthreads();
        float xx = xxs;

        float bd = 3.4e38f;
        int   bj = 0;
#pragma unroll 1
        for (int q = 0; q < 4; q++) {
            int j = tid * 4 + q;
            const float* e = embed + (size_t)j * DIMD;
            float xe = 0.f;
            for (int k = 0; k < 128; k++)
                xe = __fadd_rn(xe, __fmul_rn(xv[k], e[k]));
            float s1 = __fadd_rn(xx, __fmul_rn(-2.0f, xe));
            float d2 = __fadd_rn(s1, g_ee[j]);
            if (d2 < bd) { bd = d2; bj = j; }
        }
        rv[tid] = bd; rix[tid] = bj;
        __syncthreads();
        for (int s = 128; s > 0; s >>= 1) {
            if (tid < s) {
                float ov = rv[tid + s]; int oj = rix[tid + s];
                if (ov < rv[tid] || (ov == rv[tid] && oj < rix[tid])) {
                    rv[tid] = ov; rix[tid] = oj;
                }
            }
            __syncthreads();
        }
        int idx = rix[0];
        if (tid == 0) {
            g_used[idx] = 1u;
            out[QELEMS + n] = (float)idx;
        }
        if (tid < 128)
            out[(size_t)b * DIMD * TT + (size_t)tid * TT + t] =
                embed[(size_t)idx * DIMD + tid];
        __syncthreads();
    }
}

// ---------------------------------------------------------------------------
// Kernel 3: deterministic final reduction -> loss, utilization
// ---------------------------------------------------------------------------
__global__ void finalize_kernel(float* __restrict__ out) {
    __shared__ float rs[512];
    __shared__ float us[512];
    int tid = threadIdx.x;
    rs[tid] = (tid < NBLK) ? g_partial[tid] : 0.f;
    us[tid] = (float)(g_used[tid] + g_used[tid + 512]);
    __syncthreads();
    for (int s = 256; s > 0; s >>= 1) {
        if (tid < s) { rs[tid] += rs[tid + s]; us[tid] += us[tid + s]; }
        __syncthreads();
    }
    if (tid == 0) {
        out[QELEMS + NTOT]     = 2.0f * rs[0] / (float)QELEMS;  // 2*mean(diff^2)
        out[QELEMS + NTOT + 1] = us[0] / (float)NC;
    }
}

// ---------------------------------------------------------------------------
extern "C" void kernel_launch(void* const* d_in, const int* in_sizes, int n_in,
                              void* d_out, int out_size) {
    (void)in_sizes; (void)n_in; (void)out_size;
    const float* x     = (const float*)d_in[0];
    const float* embed = (const float*)d_in[1];
    float*       out   = (float*)d_out;

    cudaFuncSetAttribute(vq_main_kernel,
                         cudaFuncAttributeMaxDynamicSharedMemorySize, SMEM_MAIN);

    prep_kernel<<<4, 256>>>(embed);
    vq_main_kernel<<<NBLK, 256, SMEM_MAIN>>>(x, embed, out);
    repair_kernel<<<148, 256>>>(x, embed, out);
    finalize_kernel<<<1, 512>>>(out);
}